// round 3
// baseline (speedup 1.0000x reference)
#include <cuda_runtime.h>

#define NN 100000
#define EE 1600000
#define HD 128
#define NL 4
#define NGR 256
#define BN_EPS 1e-5f

// ---------------- device scratch (no allocations allowed) ----------------
__device__ float g_hw[NN * HD];   // GEMM output (pre-aggregation)
__device__ float g_h[NN * HD];    // aggregated activations (next layer input)
__device__ int   g_deg[NN];
__device__ float g_dinv[NN];
__device__ int   g_rowtmp[NN];
__device__ int   g_rowptr[NN];
__device__ int   g_cursor[NN];
__device__ int   g_bsum[128];
__device__ int   g_esrc[EE];
__device__ float g_enorm[EE];
__device__ float g_pool[NGR * 3 * HD];

// ---------------- CSR construction ----------------
__global__ void k_zero_deg() {
    int i = blockIdx.x * blockDim.x + threadIdx.x;
    if (i < NN) g_deg[i] = 0;
}

__global__ void k_hist(const int* __restrict__ ei) {
    int e = blockIdx.x * blockDim.x + threadIdx.x;
    if (e < EE) atomicAdd(&g_deg[ei[EE + e]], 1);
}

__global__ void k_dinv() {
    int i = blockIdx.x * blockDim.x + threadIdx.x;
    if (i < NN) g_dinv[i] = rsqrtf((float)(g_deg[i] + 1));  // +1 self loop
}

__global__ void k_scan1() {
    __shared__ int s[1024];
    int t = threadIdx.x;
    int idx = blockIdx.x * 1024 + t;
    int v = (idx < NN) ? g_deg[idx] : 0;
    s[t] = v;
    __syncthreads();
    for (int off = 1; off < 1024; off <<= 1) {
        int y = (t >= off) ? s[t - off] : 0;
        __syncthreads();
        s[t] += y;
        __syncthreads();
    }
    if (idx < NN) g_rowtmp[idx] = s[t];
    if (t == 1023) g_bsum[blockIdx.x] = s[1023];
}

__global__ void k_scan2(int nb) {
    int run = 0;
    for (int b = 0; b < nb; b++) {
        int t = g_bsum[b];
        g_bsum[b] = run;
        run += t;
    }
}

__global__ void k_scan3() {
    int i = blockIdx.x * blockDim.x + threadIdx.x;
    if (i < NN) {
        int ex = g_rowtmp[i] - g_deg[i] + g_bsum[i >> 10];
        g_rowptr[i] = ex;
        g_cursor[i] = ex;
    }
}

__global__ void k_scatter(const int* __restrict__ ei) {
    int e = blockIdx.x * blockDim.x + threadIdx.x;
    if (e < EE) {
        int src = ei[e];
        int dst = ei[EE + e];
        int pos = atomicAdd(&g_cursor[dst], 1);
        g_esrc[pos] = src;
        g_enorm[pos] = g_dinv[src] * g_dinv[dst];
    }
}

// ---------------- GEMM: out[N,128] = in[N,128] @ W[128,128] ----------------
// block tile 128 rows x 128 cols, 256 threads, 8x8 register tiles.
// sA stored transposed [k][row], sW row-major [k][col]. 128 KB dynamic smem.
// in == nullptr -> read from g_h (device global), avoiding host symbol lookup.
__global__ void __launch_bounds__(256) k_gemm(const float* __restrict__ in,
                                              const float* __restrict__ w,
                                              float* __restrict__ out) {
    extern __shared__ float sm[];
    float* sA = sm;            // 128*128
    float* sW = sm + 16384;    // 128*128
    int tid = threadIdx.x;
    int row0 = blockIdx.x * 128;

    const float* src_in = (in != nullptr) ? in : (const float*)g_h;

    // load W (row-major copy)
    const float4* w4 = (const float4*)w;
    float4* sW4 = (float4*)sW;
    #pragma unroll
    for (int i = tid; i < 4096; i += 256) sW4[i] = w4[i];

    // load A with transpose
    #pragma unroll
    for (int i = tid; i < 4096; i += 256) {
        int r = i >> 5;     // 0..127
        int k4 = i & 31;    // 0..31
        int row = row0 + r;
        float4 v = make_float4(0.f, 0.f, 0.f, 0.f);
        if (row < NN) v = *(const float4*)&src_in[row * HD + k4 * 4];
        sA[(k4 * 4 + 0) * 128 + r] = v.x;
        sA[(k4 * 4 + 1) * 128 + r] = v.y;
        sA[(k4 * 4 + 2) * 128 + r] = v.z;
        sA[(k4 * 4 + 3) * 128 + r] = v.w;
    }
    __syncthreads();

    int ty = tid >> 4, tx = tid & 15;
    float acc[8][8];
    #pragma unroll
    for (int i = 0; i < 8; i++)
        #pragma unroll
        for (int j = 0; j < 8; j++) acc[i][j] = 0.f;

    #pragma unroll 4
    for (int k = 0; k < 128; k++) {
        float4 a0 = *(const float4*)&sA[k * 128 + ty * 8];
        float4 a1 = *(const float4*)&sA[k * 128 + ty * 8 + 4];
        float4 b0 = *(const float4*)&sW[k * 128 + tx * 8];
        float4 b1 = *(const float4*)&sW[k * 128 + tx * 8 + 4];
        float a[8] = {a0.x, a0.y, a0.z, a0.w, a1.x, a1.y, a1.z, a1.w};
        float b[8] = {b0.x, b0.y, b0.z, b0.w, b1.x, b1.y, b1.z, b1.w};
        #pragma unroll
        for (int i = 0; i < 8; i++)
            #pragma unroll
            for (int j = 0; j < 8; j++) acc[i][j] += a[i] * b[j];
    }

    #pragma unroll
    for (int i = 0; i < 8; i++) {
        int row = row0 + ty * 8 + i;
        if (row < NN) {
            *(float4*)&out[row * HD + tx * 8] =
                make_float4(acc[i][0], acc[i][1], acc[i][2], acc[i][3]);
            *(float4*)&out[row * HD + tx * 8 + 4] =
                make_float4(acc[i][4], acc[i][5], acc[i][6], acc[i][7]);
        }
    }
}

// ---------------- aggregation + bias + BN + ReLU (warp per node) ----------------
__global__ void __launch_bounds__(256) k_agg(const float* __restrict__ bias,
                                             const float* __restrict__ gamma,
                                             const float* __restrict__ beta,
                                             const float* __restrict__ mean,
                                             const float* __restrict__ var) {
    int warp = (blockIdx.x * blockDim.x + threadIdx.x) >> 5;
    if (warp >= NN) return;
    int lane = threadIdx.x & 31;
    int i = warp;

    const float4* hw4 = (const float4*)g_hw;
    float di = g_dinv[i];
    float self = di * di;
    float4 acc = hw4[i * 32 + lane];
    acc.x *= self; acc.y *= self; acc.z *= self; acc.w *= self;

    int s = g_rowptr[i];
    int e = s + g_deg[i];
    int p = s;
    for (; p + 3 < e; p += 4) {
        int s0 = g_esrc[p], s1 = g_esrc[p + 1], s2 = g_esrc[p + 2], s3 = g_esrc[p + 3];
        float n0 = g_enorm[p], n1 = g_enorm[p + 1], n2 = g_enorm[p + 2], n3 = g_enorm[p + 3];
        float4 v0 = hw4[s0 * 32 + lane];
        float4 v1 = hw4[s1 * 32 + lane];
        float4 v2 = hw4[s2 * 32 + lane];
        float4 v3 = hw4[s3 * 32 + lane];
        acc.x += n0 * v0.x + n1 * v1.x + n2 * v2.x + n3 * v3.x;
        acc.y += n0 * v0.y + n1 * v1.y + n2 * v2.y + n3 * v3.y;
        acc.z += n0 * v0.z + n1 * v1.z + n2 * v2.z + n3 * v3.z;
        acc.w += n0 * v0.w + n1 * v1.w + n2 * v2.w + n3 * v3.w;
    }
    for (; p < e; p++) {
        int sj = g_esrc[p];
        float nm = g_enorm[p];
        float4 v = hw4[sj * 32 + lane];
        acc.x += nm * v.x; acc.y += nm * v.y; acc.z += nm * v.z; acc.w += nm * v.w;
    }

    int c = lane * 4;
    float4 bs = *(const float4*)&bias[c];
    float4 gm = *(const float4*)&gamma[c];
    float4 bt = *(const float4*)&beta[c];
    float4 mn = *(const float4*)&mean[c];
    float4 vr = *(const float4*)&var[c];

    float4 o;
    o.x = fmaxf((acc.x + bs.x - mn.x) * (gm.x * rsqrtf(vr.x + BN_EPS)) + bt.x, 0.f);
    o.y = fmaxf((acc.y + bs.y - mn.y) * (gm.y * rsqrtf(vr.y + BN_EPS)) + bt.y, 0.f);
    o.z = fmaxf((acc.z + bs.z - mn.z) * (gm.z * rsqrtf(vr.z + BN_EPS)) + bt.z, 0.f);
    o.w = fmaxf((acc.w + bs.w - mn.w) * (gm.w * rsqrtf(vr.w + BN_EPS)) + bt.w, 0.f);
    *((float4*)&g_h[i * HD + c]) = o;
}

// ---------------- pooling (batch sorted -> binary search ranges) ----------------
__global__ void __launch_bounds__(128) k_pool(const int* __restrict__ batch) {
    int b = blockIdx.x;
    int c = threadIdx.x;

    int lo = 0, hi = NN;
    while (lo < hi) { int m = (lo + hi) >> 1; if (batch[m] < b) lo = m + 1; else hi = m; }
    int start = lo;
    hi = NN;
    while (lo < hi) { int m = (lo + hi) >> 1; if (batch[m] < b + 1) lo = m + 1; else hi = m; }
    int end = lo;

    float sum = 0.f, mx = 0.f;  // post-ReLU values are >= 0
    for (int n = start; n < end; n++) {
        float v = g_h[n * HD + c];
        sum += v;
        mx = fmaxf(mx, v);
    }
    float cnt = (float)(end - start);
    float mean = (cnt > 0.f) ? sum / cnt : 0.f;
    g_pool[b * 384 + c] = mean;
    g_pool[b * 384 + 128 + c] = mx;
    g_pool[b * 384 + 256 + c] = sum;
}

// ---------------- fused MLP head (block per graph) ----------------
__global__ void __launch_bounds__(128) k_mlp(const float* __restrict__ fc1w,
                                             const float* __restrict__ fc1b,
                                             const float* __restrict__ fc2w,
                                             const float* __restrict__ fc2b,
                                             const float* __restrict__ fc3w,
                                             const float* __restrict__ fc3b,
                                             float* __restrict__ out) {
    __shared__ float sg[384];
    __shared__ float s1[128];
    __shared__ float s2[64];
    int b = blockIdx.x, t = threadIdx.x;
    sg[t] = g_pool[b * 384 + t];
    sg[t + 128] = g_pool[b * 384 + 128 + t];
    sg[t + 256] = g_pool[b * 384 + 256 + t];
    __syncthreads();

    float acc = fc1b[t];
    #pragma unroll 8
    for (int k = 0; k < 384; k++) acc += sg[k] * fc1w[k * 128 + t];
    s1[t] = fmaxf(acc, 0.f);
    __syncthreads();

    if (t < 64) {
        float a2 = fc2b[t];
        #pragma unroll 8
        for (int k = 0; k < 128; k++) a2 += s1[k] * fc2w[k * 64 + t];
        s2[t] = fmaxf(a2, 0.f);
    }
    __syncthreads();

    if (t == 0) {
        float a3 = fc3b[0];
        #pragma unroll
        for (int k = 0; k < 64; k++) a3 += s2[k] * fc3w[k];
        out[b] = a3;
    }
}

// ---------------- launch ----------------
extern "C" void kernel_launch(void* const* d_in, const int* in_sizes, int n_in,
                              void* d_out, int out_size) {
    const float* x     = (const float*)d_in[0];
    const int*   ei    = (const int*)d_in[1];
    const int*   batch = (const int*)d_in[2];
    const float* convw = (const float*)d_in[3];
    const float* convb = (const float*)d_in[4];
    const float* gamma = (const float*)d_in[5];
    const float* beta  = (const float*)d_in[6];
    const float* mean  = (const float*)d_in[7];
    const float* var   = (const float*)d_in[8];
    const float* fc1w  = (const float*)d_in[9];
    const float* fc1b  = (const float*)d_in[10];
    const float* fc2w  = (const float*)d_in[11];
    const float* fc2b  = (const float*)d_in[12];
    const float* fc3w  = (const float*)d_in[13];
    const float* fc3b  = (const float*)d_in[14];
    float* out = (float*)d_out;

    static bool attr_set = false;
    if (!attr_set) {
        cudaFuncSetAttribute(k_gemm, cudaFuncAttributeMaxDynamicSharedMemorySize, 131072);
        attr_set = true;
    }

    // CSR build
    k_zero_deg<<<(NN + 255) / 256, 256>>>();
    k_hist<<<(EE + 255) / 256, 256>>>(ei);
    k_dinv<<<(NN + 255) / 256, 256>>>();
    k_scan1<<<(NN + 1023) / 1024, 1024>>>();
    k_scan2<<<1, 1>>>((NN + 1023) / 1024);
    k_scan3<<<(NN + 255) / 256, 256>>>();
    k_scatter<<<(EE + 255) / 256, 256>>>(ei);

    // layers: GEMM writes g_hw via out param; agg reads g_hw, writes g_h.
    // k_gemm input: layer 0 reads x, later layers read g_h (in == nullptr).
    const int gemm_blocks = (NN + 127) / 128;
    const int agg_blocks = (NN * 32 + 255) / 256;  // warp per node
    for (int l = 0; l < NL; l++) {
        const float* in = (l == 0) ? x : nullptr;
        float* hw_out;
        cudaGetSymbolAddress((void**)&hw_out, g_hw);
        k_gemm<<<gemm_blocks, 256, 131072>>>(in, convw + l * HD * HD, hw_out);
        k_agg<<<agg_blocks, 256>>>(convb + l * HD, gamma + l * HD, beta + l * HD,
                                   mean + l * HD, var + l * HD);
    }

    // pooling + MLP head
    k_pool<<<NGR, 128>>>(batch);
    k_mlp<<<NGR, 128>>>(fc1w, fc1b, fc2w, fc2b, fc3w, fc3b, out);
}

// round 4
// speedup vs baseline: 1.6120x; 1.6120x over previous
#include <cuda_runtime.h>

#define NN 100000
#define EE 1600000
#define HD 128
#define NL 4
#define NGR 256
#define BN_EPS 1e-5f

// ---------------- device scratch (no allocations allowed) ----------------
__device__ float g_hw[NN * HD];   // GEMM output (pre-aggregation)
__device__ float g_h[NN * HD];    // aggregated activations (next layer input)
__device__ int   g_deg[NN];
__device__ float g_dinv[NN];
__device__ int   g_rowtmp[NN];
__device__ int   g_rowptr[NN];
__device__ int   g_cursor[NN];
__device__ int   g_bsum[128];
__device__ int   g_esrc[EE];
__device__ float g_enorm[EE];
__device__ float g_pool[NGR * 3 * HD];

// ---------------- CSR construction ----------------
__global__ void k_zero_deg() {
    int i = blockIdx.x * blockDim.x + threadIdx.x;
    if (i < NN) g_deg[i] = 0;
}

__global__ void k_hist(const int* __restrict__ ei) {
    int e = blockIdx.x * blockDim.x + threadIdx.x;
    if (e < EE) atomicAdd(&g_deg[ei[EE + e]], 1);
}

__global__ void k_dinv() {
    int i = blockIdx.x * blockDim.x + threadIdx.x;
    if (i < NN) g_dinv[i] = rsqrtf((float)(g_deg[i] + 1));  // +1 self loop
}

__global__ void k_scan1() {
    __shared__ int s[1024];
    int t = threadIdx.x;
    int idx = blockIdx.x * 1024 + t;
    int v = (idx < NN) ? g_deg[idx] : 0;
    s[t] = v;
    __syncthreads();
    for (int off = 1; off < 1024; off <<= 1) {
        int y = (t >= off) ? s[t - off] : 0;
        __syncthreads();
        s[t] += y;
        __syncthreads();
    }
    if (idx < NN) g_rowtmp[idx] = s[t];
    if (t == 1023) g_bsum[blockIdx.x] = s[1023];
}

__global__ void k_scan2(int nb) {
    int run = 0;
    for (int b = 0; b < nb; b++) {
        int t = g_bsum[b];
        g_bsum[b] = run;
        run += t;
    }
}

__global__ void k_scan3() {
    int i = blockIdx.x * blockDim.x + threadIdx.x;
    if (i < NN) {
        int ex = g_rowtmp[i] - g_deg[i] + g_bsum[i >> 10];
        g_rowptr[i] = ex;
        g_cursor[i] = ex;
    }
}

__global__ void k_scatter(const int* __restrict__ ei) {
    int e = blockIdx.x * blockDim.x + threadIdx.x;
    if (e < EE) {
        int src = ei[e];
        int dst = ei[EE + e];
        int pos = atomicAdd(&g_cursor[dst], 1);
        g_esrc[pos] = src;
        g_enorm[pos] = g_dinv[src] * g_dinv[dst];
    }
}

// ---------------- tf32 tensor-core GEMM ----------------
// out[N,128] = in[N,128] @ W[128,128], block tile 128x128, K=128 in one shot.
// 8 warps: warp (wm,wn) owns a 32x64 sub-tile -> 2x8 m16n8k8 mma tiles.
// smem padded to stride 132 for conflict-free fragment loads.

__device__ __forceinline__ unsigned f2tf(float x) {
    unsigned u;
    asm("cvt.rna.tf32.f32 %0, %1;" : "=r"(u) : "f"(x));
    return u;
}

#define GEMM_SMEM (2 * 128 * 132 * 4)

__global__ void __launch_bounds__(256) k_gemm(const float* __restrict__ in,
                                              const float* __restrict__ w,
                                              float* __restrict__ out) {
    extern __shared__ unsigned sm[];
    unsigned* sA = sm;               // [128][132]  row r, k
    unsigned* sW = sm + 128 * 132;   // [128][132]  k, col n
    const float* src_in = (in != nullptr) ? in : (const float*)g_h;
    int tid = threadIdx.x;
    int row0 = blockIdx.x * 128;

    // W[k][n] -> sW[k*132+n], converted to tf32
    #pragma unroll
    for (int i = tid; i < 4096; i += 256) {
        int k = i >> 5, n4 = (i & 31) * 4;
        float4 v = *(const float4*)&w[k * 128 + n4];
        uint4 u = make_uint4(f2tf(v.x), f2tf(v.y), f2tf(v.z), f2tf(v.w));
        *(uint4*)&sW[k * 132 + n4] = u;
    }
    // A[r][k] -> sA[r*132+k]
    #pragma unroll
    for (int i = tid; i < 4096; i += 256) {
        int r = i >> 5, k4 = (i & 31) * 4;
        int row = row0 + r;
        float4 v = make_float4(0.f, 0.f, 0.f, 0.f);
        if (row < NN) v = *(const float4*)&src_in[row * HD + k4];
        uint4 u = make_uint4(f2tf(v.x), f2tf(v.y), f2tf(v.z), f2tf(v.w));
        *(uint4*)&sA[r * 132 + k4] = u;
    }
    __syncthreads();

    int lane = tid & 31, warp = tid >> 5;
    int wm = warp & 3, wn = warp >> 2;   // wm: 0..3 (M), wn: 0..1 (N)
    int lr = lane >> 2, lc = lane & 3;

    float acc[2][8][4];
    #pragma unroll
    for (int mt = 0; mt < 2; mt++)
        #pragma unroll
        for (int nt = 0; nt < 8; nt++)
            #pragma unroll
            for (int q = 0; q < 4; q++) acc[mt][nt][q] = 0.f;

    #pragma unroll
    for (int ks = 0; ks < 16; ks++) {
        int k0 = ks * 8;
        unsigned a[2][4];
        #pragma unroll
        for (int mt = 0; mt < 2; mt++) {
            int r = wm * 32 + mt * 16 + lr;
            a[mt][0] = sA[r * 132 + k0 + lc];
            a[mt][1] = sA[(r + 8) * 132 + k0 + lc];
            a[mt][2] = sA[r * 132 + k0 + 4 + lc];
            a[mt][3] = sA[(r + 8) * 132 + k0 + 4 + lc];
        }
        #pragma unroll
        for (int nt = 0; nt < 8; nt++) {
            int n = wn * 64 + nt * 8 + lr;
            unsigned b0 = sW[(k0 + lc) * 132 + n];
            unsigned b1 = sW[(k0 + 4 + lc) * 132 + n];
            #pragma unroll
            for (int mt = 0; mt < 2; mt++) {
                asm volatile(
                    "mma.sync.aligned.m16n8k8.row.col.f32.tf32.tf32.f32 "
                    "{%0,%1,%2,%3}, {%4,%5,%6,%7}, {%8,%9}, {%0,%1,%2,%3};"
                    : "+f"(acc[mt][nt][0]), "+f"(acc[mt][nt][1]),
                      "+f"(acc[mt][nt][2]), "+f"(acc[mt][nt][3])
                    : "r"(a[mt][0]), "r"(a[mt][1]), "r"(a[mt][2]), "r"(a[mt][3]),
                      "r"(b0), "r"(b1));
            }
        }
    }

    // epilogue: c0/c1 -> (row, 2lc), c2/c3 -> (row+8, 2lc)
    #pragma unroll
    for (int mt = 0; mt < 2; mt++) {
        int r1 = row0 + wm * 32 + mt * 16 + lr;
        int r2 = r1 + 8;
        #pragma unroll
        for (int nt = 0; nt < 8; nt++) {
            int col = wn * 64 + nt * 8 + 2 * lc;
            if (r1 < NN)
                *(float2*)&out[r1 * HD + col] = make_float2(acc[mt][nt][0], acc[mt][nt][1]);
            if (r2 < NN)
                *(float2*)&out[r2 * HD + col] = make_float2(acc[mt][nt][2], acc[mt][nt][3]);
        }
    }
}

// ---------------- aggregation + bias + BN + ReLU (warp per node) ----------------
__global__ void __launch_bounds__(256) k_agg(const float* __restrict__ bias,
                                             const float* __restrict__ gamma,
                                             const float* __restrict__ beta,
                                             const float* __restrict__ mean,
                                             const float* __restrict__ var) {
    int warp = (blockIdx.x * blockDim.x + threadIdx.x) >> 5;
    if (warp >= NN) return;
    int lane = threadIdx.x & 31;
    int i = warp;

    const float4* hw4 = (const float4*)g_hw;
    float di = g_dinv[i];
    float self = di * di;
    float4 acc = hw4[i * 32 + lane];
    acc.x *= self; acc.y *= self; acc.z *= self; acc.w *= self;

    int s = g_rowptr[i];
    int e = s + g_deg[i];
    int p = s;
    for (; p + 3 < e; p += 4) {
        int s0 = g_esrc[p], s1 = g_esrc[p + 1], s2 = g_esrc[p + 2], s3 = g_esrc[p + 3];
        float n0 = g_enorm[p], n1 = g_enorm[p + 1], n2 = g_enorm[p + 2], n3 = g_enorm[p + 3];
        float4 v0 = hw4[s0 * 32 + lane];
        float4 v1 = hw4[s1 * 32 + lane];
        float4 v2 = hw4[s2 * 32 + lane];
        float4 v3 = hw4[s3 * 32 + lane];
        acc.x += n0 * v0.x + n1 * v1.x + n2 * v2.x + n3 * v3.x;
        acc.y += n0 * v0.y + n1 * v1.y + n2 * v2.y + n3 * v3.y;
        acc.z += n0 * v0.z + n1 * v1.z + n2 * v2.z + n3 * v3.z;
        acc.w += n0 * v0.w + n1 * v1.w + n2 * v2.w + n3 * v3.w;
    }
    for (; p < e; p++) {
        int sj = g_esrc[p];
        float nm = g_enorm[p];
        float4 v = hw4[sj * 32 + lane];
        acc.x += nm * v.x; acc.y += nm * v.y; acc.z += nm * v.z; acc.w += nm * v.w;
    }

    int c = lane * 4;
    float4 bs = *(const float4*)&bias[c];
    float4 gm = *(const float4*)&gamma[c];
    float4 bt = *(const float4*)&beta[c];
    float4 mn = *(const float4*)&mean[c];
    float4 vr = *(const float4*)&var[c];

    float4 o;
    o.x = fmaxf((acc.x + bs.x - mn.x) * (gm.x * rsqrtf(vr.x + BN_EPS)) + bt.x, 0.f);
    o.y = fmaxf((acc.y + bs.y - mn.y) * (gm.y * rsqrtf(vr.y + BN_EPS)) + bt.y, 0.f);
    o.z = fmaxf((acc.z + bs.z - mn.z) * (gm.z * rsqrtf(vr.z + BN_EPS)) + bt.z, 0.f);
    o.w = fmaxf((acc.w + bs.w - mn.w) * (gm.w * rsqrtf(vr.w + BN_EPS)) + bt.w, 0.f);
    *((float4*)&g_h[i * HD + c]) = o;
}

// ---------------- pooling (batch sorted -> binary search ranges) ----------------
__global__ void __launch_bounds__(128) k_pool(const int* __restrict__ batch) {
    int b = blockIdx.x;
    int c = threadIdx.x;

    int lo = 0, hi = NN;
    while (lo < hi) { int m = (lo + hi) >> 1; if (batch[m] < b) lo = m + 1; else hi = m; }
    int start = lo;
    hi = NN;
    while (lo < hi) { int m = (lo + hi) >> 1; if (batch[m] < b + 1) lo = m + 1; else hi = m; }
    int end = lo;

    float s0 = 0.f, s1 = 0.f, s2 = 0.f, s3 = 0.f;
    float m0 = 0.f, m1 = 0.f, m2 = 0.f, m3 = 0.f;  // post-ReLU >= 0
    int n = start;
    for (; n + 3 < end; n += 4) {
        float v0 = g_h[(n + 0) * HD + c];
        float v1 = g_h[(n + 1) * HD + c];
        float v2 = g_h[(n + 2) * HD + c];
        float v3 = g_h[(n + 3) * HD + c];
        s0 += v0; s1 += v1; s2 += v2; s3 += v3;
        m0 = fmaxf(m0, v0); m1 = fmaxf(m1, v1);
        m2 = fmaxf(m2, v2); m3 = fmaxf(m3, v3);
    }
    for (; n < end; n++) {
        float v = g_h[n * HD + c];
        s0 += v;
        m0 = fmaxf(m0, v);
    }
    float sum = (s0 + s1) + (s2 + s3);
    float mx = fmaxf(fmaxf(m0, m1), fmaxf(m2, m3));
    float cnt = (float)(end - start);
    float mean = (cnt > 0.f) ? sum / cnt : 0.f;
    g_pool[b * 384 + c] = mean;
    g_pool[b * 384 + 128 + c] = mx;
    g_pool[b * 384 + 256 + c] = sum;
}

// ---------------- fused MLP head (block per graph) ----------------
__global__ void __launch_bounds__(128) k_mlp(const float* __restrict__ fc1w,
                                             const float* __restrict__ fc1b,
                                             const float* __restrict__ fc2w,
                                             const float* __restrict__ fc2b,
                                             const float* __restrict__ fc3w,
                                             const float* __restrict__ fc3b,
                                             float* __restrict__ out) {
    __shared__ float sg[384];
    __shared__ float s1[128];
    __shared__ float s2[64];
    int b = blockIdx.x, t = threadIdx.x;
    sg[t] = g_pool[b * 384 + t];
    sg[t + 128] = g_pool[b * 384 + 128 + t];
    sg[t + 256] = g_pool[b * 384 + 256 + t];
    __syncthreads();

    float acc = fc1b[t];
    #pragma unroll 8
    for (int k = 0; k < 384; k++) acc += sg[k] * fc1w[k * 128 + t];
    s1[t] = fmaxf(acc, 0.f);
    __syncthreads();

    if (t < 64) {
        float a2 = fc2b[t];
        #pragma unroll 8
        for (int k = 0; k < 128; k++) a2 += s1[k] * fc2w[k * 64 + t];
        s2[t] = fmaxf(a2, 0.f);
    }
    __syncthreads();

    if (t == 0) {
        float a3 = fc3b[0];
        #pragma unroll
        for (int k = 0; k < 64; k++) a3 += s2[k] * fc3w[k];
        out[b] = a3;
    }
}

// ---------------- launch ----------------
extern "C" void kernel_launch(void* const* d_in, const int* in_sizes, int n_in,
                              void* d_out, int out_size) {
    const float* x     = (const float*)d_in[0];
    const int*   ei    = (const int*)d_in[1];
    const int*   batch = (const int*)d_in[2];
    const float* convw = (const float*)d_in[3];
    const float* convb = (const float*)d_in[4];
    const float* gamma = (const float*)d_in[5];
    const float* beta  = (const float*)d_in[6];
    const float* mean  = (const float*)d_in[7];
    const float* var   = (const float*)d_in[8];
    const float* fc1w  = (const float*)d_in[9];
    const float* fc1b  = (const float*)d_in[10];
    const float* fc2w  = (const float*)d_in[11];
    const float* fc2b  = (const float*)d_in[12];
    const float* fc3w  = (const float*)d_in[13];
    const float* fc3b  = (const float*)d_in[14];
    float* out = (float*)d_out;

    cudaFuncSetAttribute(k_gemm, cudaFuncAttributeMaxDynamicSharedMemorySize, GEMM_SMEM);

    float* hw_out;
    cudaGetSymbolAddress((void**)&hw_out, g_hw);

    // CSR build
    k_zero_deg<<<(NN + 255) / 256, 256>>>();
    k_hist<<<(EE + 255) / 256, 256>>>(ei);
    k_dinv<<<(NN + 255) / 256, 256>>>();
    k_scan1<<<(NN + 1023) / 1024, 1024>>>();
    k_scan2<<<1, 1>>>((NN + 1023) / 1024);
    k_scan3<<<(NN + 255) / 256, 256>>>();
    k_scatter<<<(EE + 255) / 256, 256>>>(ei);

    // layers
    const int gemm_blocks = (NN + 127) / 128;
    const int agg_blocks = (NN * 32 + 255) / 256;  // warp per node
    for (int l = 0; l < NL; l++) {
        const float* in = (l == 0) ? x : nullptr;
        k_gemm<<<gemm_blocks, 256, GEMM_SMEM>>>(in, convw + l * HD * HD, hw_out);
        k_agg<<<agg_blocks, 256>>>(convb + l * HD, gamma + l * HD, beta + l * HD,
                                   mean + l * HD, var + l * HD);
    }

    // pooling + MLP head
    k_pool<<<NGR, 128>>>(batch);
    k_mlp<<<NGR, 128>>>(fc1w, fc1b, fc2w, fc2b, fc3w, fc3b, out);
}

// round 5
// speedup vs baseline: 1.8273x; 1.1336x over previous
#include <cuda_runtime.h>
#include <cuda_fp16.h>

#define NN 100000
#define EE 1600000
#define HD 128
#define NL 4
#define NGR 256
#define BN_EPS 1e-5f

// ---------------- device scratch (no allocations allowed) ----------------
__device__ __half g_hw[NN * HD];  // GEMM output (pre-aggregation), fp16
__device__ float  g_h[NN * HD];   // aggregated activations (next layer input)
__device__ int    g_deg[NN];
__device__ float  g_dinv[NN];
__device__ int    g_rowtmp[NN];
__device__ int    g_rowptr[NN];
__device__ int    g_cursor[NN];
__device__ int    g_bsum[128];
__device__ int    g_esrc[EE];
__device__ float  g_enorm[EE];
__device__ float  g_pool[NGR * 3 * HD];

// ---------------- CSR construction ----------------
__global__ void k_zero_deg() {
    int i = blockIdx.x * blockDim.x + threadIdx.x;
    if (i < NN) g_deg[i] = 0;
}

__global__ void k_hist(const int* __restrict__ ei) {
    int e = blockIdx.x * blockDim.x + threadIdx.x;
    if (e < EE) atomicAdd(&g_deg[ei[EE + e]], 1);
}

__global__ void k_dinv() {
    int i = blockIdx.x * blockDim.x + threadIdx.x;
    if (i < NN) g_dinv[i] = rsqrtf((float)(g_deg[i] + 1));  // +1 self loop
}

__global__ void k_scan1() {
    __shared__ int s[1024];
    int t = threadIdx.x;
    int idx = blockIdx.x * 1024 + t;
    int v = (idx < NN) ? g_deg[idx] : 0;
    s[t] = v;
    __syncthreads();
    for (int off = 1; off < 1024; off <<= 1) {
        int y = (t >= off) ? s[t - off] : 0;
        __syncthreads();
        s[t] += y;
        __syncthreads();
    }
    if (idx < NN) g_rowtmp[idx] = s[t];
    if (t == 1023) g_bsum[blockIdx.x] = s[1023];
}

__global__ void k_scan2(int nb) {
    int run = 0;
    for (int b = 0; b < nb; b++) {
        int t = g_bsum[b];
        g_bsum[b] = run;
        run += t;
    }
}

__global__ void k_scan3() {
    int i = blockIdx.x * blockDim.x + threadIdx.x;
    if (i < NN) {
        int ex = g_rowtmp[i] - g_deg[i] + g_bsum[i >> 10];
        g_rowptr[i] = ex;
        g_cursor[i] = ex;
    }
}

__global__ void k_scatter(const int* __restrict__ ei) {
    int e = blockIdx.x * blockDim.x + threadIdx.x;
    if (e < EE) {
        int src = ei[e];
        int dst = ei[EE + e];
        int pos = atomicAdd(&g_cursor[dst], 1);
        g_esrc[pos] = src;
        g_enorm[pos] = g_dinv[src] * g_dinv[dst];
    }
}

// ---------------- tf32 tensor-core GEMM, fp16 output ----------------
// out[N,128] = in[N,128] @ W[128,128], block tile 128x128, K=128 in one shot.
// 8 warps: warp (wm,wn) owns a 32x64 sub-tile -> 2x8 m16n8k8 mma tiles.

__device__ __forceinline__ unsigned f2tf(float x) {
    unsigned u;
    asm("cvt.rna.tf32.f32 %0, %1;" : "=r"(u) : "f"(x));
    return u;
}

#define GEMM_SMEM (2 * 128 * 132 * 4)

__global__ void __launch_bounds__(256) k_gemm(const float* __restrict__ in,
                                              const float* __restrict__ w,
                                              __half* __restrict__ out) {
    extern __shared__ unsigned sm[];
    unsigned* sA = sm;               // [128][132]  row r, k
    unsigned* sW = sm + 128 * 132;   // [128][132]  k, col n
    const float* src_in = (in != nullptr) ? in : (const float*)g_h;
    int tid = threadIdx.x;
    int row0 = blockIdx.x * 128;

    // W[k][n] -> sW[k*132+n], converted to tf32
    #pragma unroll
    for (int i = tid; i < 4096; i += 256) {
        int k = i >> 5, n4 = (i & 31) * 4;
        float4 v = *(const float4*)&w[k * 128 + n4];
        uint4 u = make_uint4(f2tf(v.x), f2tf(v.y), f2tf(v.z), f2tf(v.w));
        *(uint4*)&sW[k * 132 + n4] = u;
    }
    // A[r][k] -> sA[r*132+k]
    #pragma unroll
    for (int i = tid; i < 4096; i += 256) {
        int r = i >> 5, k4 = (i & 31) * 4;
        int row = row0 + r;
        float4 v = make_float4(0.f, 0.f, 0.f, 0.f);
        if (row < NN) v = *(const float4*)&src_in[row * HD + k4];
        uint4 u = make_uint4(f2tf(v.x), f2tf(v.y), f2tf(v.z), f2tf(v.w));
        *(uint4*)&sA[r * 132 + k4] = u;
    }
    __syncthreads();

    int lane = tid & 31, warp = tid >> 5;
    int wm = warp & 3, wn = warp >> 2;   // wm: 0..3 (M), wn: 0..1 (N)
    int lr = lane >> 2, lc = lane & 3;

    float acc[2][8][4];
    #pragma unroll
    for (int mt = 0; mt < 2; mt++)
        #pragma unroll
        for (int nt = 0; nt < 8; nt++)
            #pragma unroll
            for (int q = 0; q < 4; q++) acc[mt][nt][q] = 0.f;

    #pragma unroll
    for (int ks = 0; ks < 16; ks++) {
        int k0 = ks * 8;
        unsigned a[2][4];
        #pragma unroll
        for (int mt = 0; mt < 2; mt++) {
            int r = wm * 32 + mt * 16 + lr;
            a[mt][0] = sA[r * 132 + k0 + lc];
            a[mt][1] = sA[(r + 8) * 132 + k0 + lc];
            a[mt][2] = sA[r * 132 + k0 + 4 + lc];
            a[mt][3] = sA[(r + 8) * 132 + k0 + 4 + lc];
        }
        #pragma unroll
        for (int nt = 0; nt < 8; nt++) {
            int n = wn * 64 + nt * 8 + lr;
            unsigned b0 = sW[(k0 + lc) * 132 + n];
            unsigned b1 = sW[(k0 + 4 + lc) * 132 + n];
            #pragma unroll
            for (int mt = 0; mt < 2; mt++) {
                asm volatile(
                    "mma.sync.aligned.m16n8k8.row.col.f32.tf32.tf32.f32 "
                    "{%0,%1,%2,%3}, {%4,%5,%6,%7}, {%8,%9}, {%0,%1,%2,%3};"
                    : "+f"(acc[mt][nt][0]), "+f"(acc[mt][nt][1]),
                      "+f"(acc[mt][nt][2]), "+f"(acc[mt][nt][3])
                    : "r"(a[mt][0]), "r"(a[mt][1]), "r"(a[mt][2]), "r"(a[mt][3]),
                      "r"(b0), "r"(b1));
            }
        }
    }

    // epilogue: c0/c1 -> (row, 2lc..2lc+1), c2/c3 -> (row+8, ...), fp16 pairs
    #pragma unroll
    for (int mt = 0; mt < 2; mt++) {
        int r1 = row0 + wm * 32 + mt * 16 + lr;
        int r2 = r1 + 8;
        #pragma unroll
        for (int nt = 0; nt < 8; nt++) {
            int col = wn * 64 + nt * 8 + 2 * lc;
            if (r1 < NN)
                *(__half2*)&out[r1 * HD + col] =
                    __floats2half2_rn(acc[mt][nt][0], acc[mt][nt][1]);
            if (r2 < NN)
                *(__half2*)&out[r2 * HD + col] =
                    __floats2half2_rn(acc[mt][nt][2], acc[mt][nt][3]);
        }
    }
}

// ---------------- aggregation + bias + BN + ReLU (warp per node, fp16 gather) ----------------
__device__ __forceinline__ void acc_edge(float4& acc, uint2 raw, float nm) {
    float2 f01 = __half22float2(*(__half2*)&raw.x);
    float2 f23 = __half22float2(*(__half2*)&raw.y);
    acc.x += nm * f01.x; acc.y += nm * f01.y;
    acc.z += nm * f23.x; acc.w += nm * f23.y;
}

__global__ void __launch_bounds__(256) k_agg(const float* __restrict__ bias,
                                             const float* __restrict__ gamma,
                                             const float* __restrict__ beta,
                                             const float* __restrict__ mean,
                                             const float* __restrict__ var) {
    int warp = (blockIdx.x * blockDim.x + threadIdx.x) >> 5;
    if (warp >= NN) return;
    int lane = threadIdx.x & 31;
    int i = warp;

    const uint2* hw2 = (const uint2*)g_hw;  // 4 halves per uint2; 32 per row
    float di = g_dinv[i];
    float self = di * di;
    float4 acc = make_float4(0.f, 0.f, 0.f, 0.f);
    acc_edge(acc, hw2[i * 32 + lane], self);

    int s = g_rowptr[i];
    int e = s + g_deg[i];
    int p = s;
    for (; p + 3 < e; p += 4) {
        int s0 = g_esrc[p], s1 = g_esrc[p + 1], s2 = g_esrc[p + 2], s3 = g_esrc[p + 3];
        float n0 = g_enorm[p], n1 = g_enorm[p + 1], n2 = g_enorm[p + 2], n3 = g_enorm[p + 3];
        uint2 v0 = hw2[s0 * 32 + lane];
        uint2 v1 = hw2[s1 * 32 + lane];
        uint2 v2 = hw2[s2 * 32 + lane];
        uint2 v3 = hw2[s3 * 32 + lane];
        acc_edge(acc, v0, n0);
        acc_edge(acc, v1, n1);
        acc_edge(acc, v2, n2);
        acc_edge(acc, v3, n3);
    }
    for (; p < e; p++) {
        acc_edge(acc, hw2[g_esrc[p] * 32 + lane], g_enorm[p]);
    }

    int c = lane * 4;
    float4 bs = *(const float4*)&bias[c];
    float4 gm = *(const float4*)&gamma[c];
    float4 bt = *(const float4*)&beta[c];
    float4 mn = *(const float4*)&mean[c];
    float4 vr = *(const float4*)&var[c];

    float4 o;
    o.x = fmaxf((acc.x + bs.x - mn.x) * (gm.x * rsqrtf(vr.x + BN_EPS)) + bt.x, 0.f);
    o.y = fmaxf((acc.y + bs.y - mn.y) * (gm.y * rsqrtf(vr.y + BN_EPS)) + bt.y, 0.f);
    o.z = fmaxf((acc.z + bs.z - mn.z) * (gm.z * rsqrtf(vr.z + BN_EPS)) + bt.z, 0.f);
    o.w = fmaxf((acc.w + bs.w - mn.w) * (gm.w * rsqrtf(vr.w + BN_EPS)) + bt.w, 0.f);
    *((float4*)&g_h[i * HD + c]) = o;
}

// ---------------- pooling (batch sorted -> binary search ranges) ----------------
__global__ void __launch_bounds__(128) k_pool(const int* __restrict__ batch) {
    int b = blockIdx.x;
    int c = threadIdx.x;

    int lo = 0, hi = NN;
    while (lo < hi) { int m = (lo + hi) >> 1; if (batch[m] < b) lo = m + 1; else hi = m; }
    int start = lo;
    hi = NN;
    while (lo < hi) { int m = (lo + hi) >> 1; if (batch[m] < b + 1) lo = m + 1; else hi = m; }
    int end = lo;

    float s0 = 0.f, s1 = 0.f, s2 = 0.f, s3 = 0.f;
    float m0 = 0.f, m1 = 0.f, m2 = 0.f, m3 = 0.f;  // post-ReLU >= 0
    int n = start;
    for (; n + 3 < end; n += 4) {
        float v0 = g_h[(n + 0) * HD + c];
        float v1 = g_h[(n + 1) * HD + c];
        float v2 = g_h[(n + 2) * HD + c];
        float v3 = g_h[(n + 3) * HD + c];
        s0 += v0; s1 += v1; s2 += v2; s3 += v3;
        m0 = fmaxf(m0, v0); m1 = fmaxf(m1, v1);
        m2 = fmaxf(m2, v2); m3 = fmaxf(m3, v3);
    }
    for (; n < end; n++) {
        float v = g_h[n * HD + c];
        s0 += v;
        m0 = fmaxf(m0, v);
    }
    float sum = (s0 + s1) + (s2 + s3);
    float mx = fmaxf(fmaxf(m0, m1), fmaxf(m2, m3));
    float cnt = (float)(end - start);
    float mean = (cnt > 0.f) ? sum / cnt : 0.f;
    g_pool[b * 384 + c] = mean;
    g_pool[b * 384 + 128 + c] = mx;
    g_pool[b * 384 + 256 + c] = sum;
}

// ---------------- fused MLP head (block per graph) ----------------
__global__ void __launch_bounds__(128) k_mlp(const float* __restrict__ fc1w,
                                             const float* __restrict__ fc1b,
                                             const float* __restrict__ fc2w,
                                             const float* __restrict__ fc2b,
                                             const float* __restrict__ fc3w,
                                             const float* __restrict__ fc3b,
                                             float* __restrict__ out) {
    __shared__ float sg[384];
    __shared__ float s1[128];
    __shared__ float s2[64];
    int b = blockIdx.x, t = threadIdx.x;
    sg[t] = g_pool[b * 384 + t];
    sg[t + 128] = g_pool[b * 384 + 128 + t];
    sg[t + 256] = g_pool[b * 384 + 256 + t];
    __syncthreads();

    float acc = fc1b[t];
    #pragma unroll 8
    for (int k = 0; k < 384; k++) acc += sg[k] * fc1w[k * 128 + t];
    s1[t] = fmaxf(acc, 0.f);
    __syncthreads();

    if (t < 64) {
        float a2 = fc2b[t];
        #pragma unroll 8
        for (int k = 0; k < 128; k++) a2 += s1[k] * fc2w[k * 64 + t];
        s2[t] = fmaxf(a2, 0.f);
    }
    __syncthreads();

    if (t == 0) {
        float a3 = fc3b[0];
        #pragma unroll
        for (int k = 0; k < 64; k++) a3 += s2[k] * fc3w[k];
        out[b] = a3;
    }
}

// ---------------- launch ----------------
extern "C" void kernel_launch(void* const* d_in, const int* in_sizes, int n_in,
                              void* d_out, int out_size) {
    const float* x     = (const float*)d_in[0];
    const int*   ei    = (const int*)d_in[1];
    const int*   batch = (const int*)d_in[2];
    const float* convw = (const float*)d_in[3];
    const float* convb = (const float*)d_in[4];
    const float* gamma = (const float*)d_in[5];
    const float* beta  = (const float*)d_in[6];
    const float* mean  = (const float*)d_in[7];
    const float* var   = (const float*)d_in[8];
    const float* fc1w  = (const float*)d_in[9];
    const float* fc1b  = (const float*)d_in[10];
    const float* fc2w  = (const float*)d_in[11];
    const float* fc2b  = (const float*)d_in[12];
    const float* fc3w  = (const float*)d_in[13];
    const float* fc3b  = (const float*)d_in[14];
    float* out = (float*)d_out;

    cudaFuncSetAttribute(k_gemm, cudaFuncAttributeMaxDynamicSharedMemorySize, GEMM_SMEM);

    __half* hw_out;
    cudaGetSymbolAddress((void**)&hw_out, g_hw);

    // CSR build
    k_zero_deg<<<(NN + 255) / 256, 256>>>();
    k_hist<<<(EE + 255) / 256, 256>>>(ei);
    k_dinv<<<(NN + 255) / 256, 256>>>();
    k_scan1<<<(NN + 1023) / 1024, 1024>>>();
    k_scan2<<<1, 1>>>((NN + 1023) / 1024);
    k_scan3<<<(NN + 255) / 256, 256>>>();
    k_scatter<<<(EE + 255) / 256, 256>>>(ei);

    // layers
    const int gemm_blocks = (NN + 127) / 128;
    const int agg_blocks = (NN * 32 + 255) / 256;  // warp per node
    for (int l = 0; l < NL; l++) {
        const float* in = (l == 0) ? x : nullptr;
        k_gemm<<<gemm_blocks, 256, GEMM_SMEM>>>(in, convw + l * HD * HD, hw_out);
        k_agg<<<agg_blocks, 256>>>(convb + l * HD, gamma + l * HD, beta + l * HD,
                                   mean + l * HD, var + l * HD);
    }

    // pooling + MLP head
    k_pool<<<NGR, 128>>>(batch);
    k_mlp<<<NGR, 128>>>(fc1w, fc1b, fc2w, fc2b, fc3w, fc3b, out);
}